// round 10
// baseline (speedup 1.0000x reference)
#include <cuda_runtime.h>
#include <math.h>

#define BB 256
#define NN 2048
#define NSUM 22   // M(6 sym), C(9), mw(3), yw(3), wsum(1)

// scratch (no allocations allowed)
__device__ float g_sq[BB];
__device__ unsigned int g_ctr;   // zero-init; monotonic across graph replays

// ---------------------------------------------------------------------------
// Pose solve for one batch from its 22 sums. fp32, tangent-form Jacobi,
// robust U construction (no division by smallest singular value).
// ---------------------------------------------------------------------------
__device__ void solve_pose(const float* __restrict__ s,
                           const float* __restrict__ tsv_in,
                           float* __restrict__ ob)
{
    float inv_ws = __fdividef(1.f, s[21]);
    float mw[3] = {s[15], s[16], s[17]};
    float yw[3] = {s[18], s[19], s[20]};

    // H = C^T - yw mw^T / ws (C[i][j] = s[6+3i+j], i=m idx, j=y idx)
    float H[3][3];
#pragma unroll
    for (int i = 0; i < 3; i++)
#pragma unroll
        for (int j = 0; j < 3; j++)
            H[i][j] = s[6 + 3 * j + i] - yw[i] * mw[j] * inv_ws;

    float mum[3], muy[3];
#pragma unroll
    for (int i = 0; i < 3; i++) { mum[i] = mw[i] * inv_ws; muy[i] = yw[i] * inv_ws; }

    // A = H^T H (symmetric)
    float A[3][3];
#pragma unroll
    for (int i = 0; i < 3; i++)
#pragma unroll
        for (int j = 0; j < 3; j++) {
            float tv = 0.f;
#pragma unroll
            for (int k = 0; k < 3; k++) tv += H[k][i] * H[k][j];
            A[i][j] = tv;
        }

    // Jacobi eigendecomposition: A = V L V^T (tangent form, fast divides)
    float V[3][3] = {{1,0,0},{0,1,0},{0,0,1}};
    for (int sweep = 0; sweep < 5; sweep++) {
#pragma unroll
        for (int r = 0; r < 3; r++) {
            int p = (r == 2) ? 1 : 0;
            int q = (r == 0) ? 1 : 2;
            float apq = A[p][q];
            float app = A[p][p], aqq = A[q][q];
            // apq == 0 -> tau huge -> t = 0 -> exact identity rotation
            float tau = (apq == 0.f) ? 3.4e38f : __fdividef(aqq - app, 2.f * apq);
            float t = __fdividef((tau >= 0.f) ? 1.f : -1.f,
                                 fabsf(tau) + sqrtf(1.f + tau * tau));
            float c = rsqrtf(1.f + t * t);
            float sn = t * c;
            float tau2 = __fdividef(sn, 1.f + c);
            A[p][p] = app - t * apq;
            A[q][q] = aqq + t * apq;
            A[p][q] = 0.f; A[q][p] = 0.f;
            int k = 3 - p - q;
            float akp = A[k][p], akq = A[k][q];
            A[k][p] = akp - sn * (akq + tau2 * akp);
            A[p][k] = A[k][p];
            A[k][q] = akq + sn * (akp - tau2 * akq);
            A[q][k] = A[k][q];
#pragma unroll
            for (int kk = 0; kk < 3; kk++) {
                float vkp = V[kk][p], vkq = V[kk][q];
                V[kk][p] = vkp - sn * (vkq + tau2 * vkp);
                V[kk][q] = vkq + sn * (vkp - tau2 * vkq);
            }
        }
    }

    // sort eigenvalues descending (columns of V follow)
    float lam[3] = {A[0][0], A[1][1], A[2][2]};
#pragma unroll
    for (int i = 0; i < 2; i++)
#pragma unroll
        for (int j = 0; j < 2 - i; j++) {
            if (lam[j] < lam[j + 1]) {
                float tl = lam[j]; lam[j] = lam[j + 1]; lam[j + 1] = tl;
#pragma unroll
                for (int k = 0; k < 3; k++) {
                    float tv = V[k][j]; V[k][j] = V[k][j + 1]; V[k][j + 1] = tv;
                }
            }
        }

    // det(V) = +1
    float detV = V[0][0] * (V[1][1] * V[2][2] - V[1][2] * V[2][1])
               - V[0][1] * (V[1][0] * V[2][2] - V[1][2] * V[2][0])
               + V[0][2] * (V[1][0] * V[2][1] - V[1][1] * V[2][0]);
    float flip = (detV < 0.f) ? -1.f : 1.f;
    V[0][2] *= flip; V[1][2] *= flip; V[2][2] *= flip;

    // u0 = normalize(H v0); u1 = normalize((H v1) perp u0); u2 = u0 x u1
    float u0[3], u1[3], u2[3];
    {
        float t0[3], t1[3];
#pragma unroll
        for (int i = 0; i < 3; i++) {
            t0[i] = H[i][0] * V[0][0] + H[i][1] * V[1][0] + H[i][2] * V[2][0];
            t1[i] = H[i][0] * V[0][1] + H[i][1] * V[1][1] + H[i][2] * V[2][1];
        }
        float n0 = rsqrtf(fmaxf(t0[0]*t0[0] + t0[1]*t0[1] + t0[2]*t0[2], 1e-30f));
#pragma unroll
        for (int i = 0; i < 3; i++) u0[i] = t0[i] * n0;
        float dot = u0[0]*t1[0] + u0[1]*t1[1] + u0[2]*t1[2];
#pragma unroll
        for (int i = 0; i < 3; i++) t1[i] -= dot * u0[i];
        float n1 = rsqrtf(fmaxf(t1[0]*t1[0] + t1[1]*t1[1] + t1[2]*t1[2], 1e-30f));
#pragma unroll
        for (int i = 0; i < 3; i++) u1[i] = t1[i] * n1;
        u2[0] = u0[1]*u1[2] - u0[2]*u1[1];
        u2[1] = u0[2]*u1[0] - u0[0]*u1[2];
        u2[2] = u0[0]*u1[1] - u0[1]*u1[0];
    }

    // R = U V^T
    float R[3][3];
#pragma unroll
    for (int i = 0; i < 3; i++) {
        float ui0 = u0[i], ui1 = u1[i], ui2 = u2[i];
#pragma unroll
        for (int j = 0; j < 3; j++)
            R[i][j] = ui0 * V[j][0] + ui1 * V[j][1] + ui2 * V[j][2];
    }

    float tt[3];
#pragma unroll
    for (int i = 0; i < 3; i++)
        tt[i] = R[i][0] * mum[0] + R[i][1] * mum[1] + R[i][2] * mum[2] - muy[i];

    float T[4][4];
#pragma unroll
    for (int i = 0; i < 3; i++) {
#pragma unroll
        for (int j = 0; j < 3; j++) T[i][j] = R[i][j];
        T[i][3] = -tt[i];
    }
    T[3][0] = 0.f; T[3][1] = 0.f; T[3][2] = 0.f; T[3][3] = 1.f;

    float Tsv[4][4];
#pragma unroll
    for (int i = 0; i < 4; i++)
#pragma unroll
        for (int j = 0; j < 4; j++) Tsv[i][j] = tsv_in[i * 4 + j];

    float Tinv[4][4];
#pragma unroll
    for (int i = 0; i < 3; i++) {
#pragma unroll
        for (int j = 0; j < 3; j++) Tinv[i][j] = Tsv[j][i];
        Tinv[i][3] = -(Tsv[0][i] * Tsv[0][3] + Tsv[1][i] * Tsv[1][3] + Tsv[2][i] * Tsv[2][3]);
    }
    Tinv[3][0] = 0.f; Tinv[3][1] = 0.f; Tinv[3][2] = 0.f; Tinv[3][3] = 1.f;

    float M1[4][4];
#pragma unroll
    for (int i = 0; i < 4; i++)
#pragma unroll
        for (int j = 0; j < 4; j++) {
            float tv = 0.f;
#pragma unroll
            for (int k = 0; k < 4; k++) tv += Tinv[i][k] * T[k][j];
            M1[i][j] = tv;
        }
#pragma unroll
    for (int i = 0; i < 4; i++)
#pragma unroll
        for (int j = 0; j < 4; j++) {
            float tv = 0.f;
#pragma unroll
            for (int k = 0; k < 4; k++) tv += M1[i][k] * Tsv[k][j];
            ob[i * 4 + j] = tv;
        }
}

// ---------------------------------------------------------------------------
__device__ __forceinline__ int sym6(int a, int c) {
    if (a > c) { int t = a; a = c; c = t; }
    return (a == 0) ? c : (a == 1) ? (2 + c) : 5;
}

__device__ __forceinline__ float q_entry(const float* __restrict__ ss, int e)
{
    int i = e / 13, j = e % 13;
    float val = 0.f;
    if (i == 0 && j == 0) {
        val = 0.f;
    } else if (i == 0 && j <= 9) {
        val = -ss[6 + (j - 1)];
    } else if (i == 0) {
        val = ss[18 + (j - 10)];
    } else if (j == 0 && i <= 9) {
        val = -ss[6 + (i - 1)];
    } else if (j == 0) {
        val = ss[18 + (i - 10)];
    } else if (i <= 9 && j <= 9) {
        int a = (i - 1) / 3, r = (i - 1) % 3;
        int bb2 = (j - 1) / 3, c = (j - 1) % 3;
        if (r == c) val = ss[sym6(a, bb2)];
    } else if (i <= 9) {
        int a = (i - 1) / 3, r = (i - 1) % 3, c = j - 10;
        if (r == c) val = -ss[15 + a];
    } else if (j <= 9) {
        int a = (j - 1) / 3, r = (j - 1) % 3, c = i - 10;
        if (r == c) val = -ss[15 + a];
    } else {
        if (i == j) val = ss[21];
    }
    return val;
}

// accumulate 4 points from a set of float4s
__device__ __forceinline__ void acc4(float* __restrict__ acc,
    const float4& wv4, const float4& a04, const float4& a14, const float4& a24,
    const float4& c04, const float4& c14, const float4& c24)
{
    const float* wvp = &wv4.x;
    const float* a0p = &a04.x; const float* a1p = &a14.x; const float* a2p = &a24.x;
    const float* c0p = &c04.x; const float* c1p = &c14.x; const float* c2p = &c24.x;
#pragma unroll
    for (int l = 0; l < 4; l++) {
        float wv = wvp[l];
        float a0 = a0p[l], a1 = a1p[l], a2 = a2p[l];
        float c0 = c0p[l], c1 = c1p[l], c2 = c2p[l];
        float w0 = wv * a0, w1 = wv * a1, w2 = wv * a2;
        acc[0]  += w0 * a0; acc[1]  += w0 * a1; acc[2]  += w0 * a2;
        acc[3]  += w1 * a1; acc[4]  += w1 * a2; acc[5]  += w2 * a2;
        acc[6]  += w0 * c0; acc[7]  += w0 * c1; acc[8]  += w0 * c2;
        acc[9]  += w1 * c0; acc[10] += w1 * c1; acc[11] += w1 * c2;
        acc[12] += w2 * c0; acc[13] += w2 * c1; acc[14] += w2 * c2;
        acc[15] += w0;      acc[16] += w1;      acc[17] += w2;
        acc[18] += wv * c0; acc[19] += wv * c1; acc[20] += wv * c2;
        acc[21] += wv;
    }
}

// ---------------------------------------------------------------------------
// SINGLE fused kernel. 256 blocks x 256 threads, __launch_bounds__(256,2)
// -> 2 blocks/SM x 148 SMs = 296 slots >= 256 blocks co-resident, so the
// grid-wide ticket-spin cannot deadlock. Reg budget 128/thread.
//
// All 14 LDG.128 are issued back-to-back (front-batched) before any FMA
// consumes them -> MLP=14 per thread for maximum DRAM latency hiding.
// ---------------------------------------------------------------------------
__global__ __launch_bounds__(256, 2) void fused_all(
    const float* __restrict__ src, const float* __restrict__ trg,
    const float* __restrict__ w, const float* __restrict__ tsv,
    float* __restrict__ tout, float* __restrict__ qout)
{
    int b = blockIdx.x;
    const int NV = NN / 4;  // 512 float4 per row; 256 threads -> 2 each
    const float4* m0 = (const float4*)(src + (size_t)b * 4 * NN);
    const float4* m1 = m0 + NV;
    const float4* m2 = m0 + 2 * NV;
    const float4* y0 = (const float4*)(trg + (size_t)b * 4 * NN);
    const float4* y1 = y0 + NV;
    const float4* y2 = y0 + 2 * NV;
    const float4* wp = (const float4*)(w + (size_t)b * NN);

    int n0 = threadIdx.x;
    int n1 = threadIdx.x + 256;

    // ---- front-batched loads: 14 LDG.128 in flight ----
    float4 wA = __ldg(wp + n0);
    float4 aA0 = __ldg(m0 + n0), aA1 = __ldg(m1 + n0), aA2 = __ldg(m2 + n0);
    float4 cA0 = __ldg(y0 + n0), cA1 = __ldg(y1 + n0), cA2 = __ldg(y2 + n0);
    float4 wB = __ldg(wp + n1);
    float4 aB0 = __ldg(m0 + n1), aB1 = __ldg(m1 + n1), aB2 = __ldg(m2 + n1);
    float4 cB0 = __ldg(y0 + n1), cB1 = __ldg(y1 + n1), cB2 = __ldg(y2 + n1);

    float acc[NSUM];
#pragma unroll
    for (int k = 0; k < NSUM; k++) acc[k] = 0.f;
    acc4(acc, wA, aA0, aA1, aA2, cA0, cA1, cA2);
    acc4(acc, wB, aB0, aB1, aB2, cB0, cB1, cB2);

    // warp reduce all 22
#pragma unroll
    for (int k = 0; k < NSUM; k++)
#pragma unroll
        for (int off = 16; off > 0; off >>= 1)
            acc[k] += __shfl_xor_sync(0xFFFFFFFFu, acc[k], off);

    __shared__ float sm[8][NSUM];
    __shared__ float sfin[NSUM];
    int wid = threadIdx.x >> 5, lane = threadIdx.x & 31;
    if (lane == 0)
#pragma unroll
        for (int k = 0; k < NSUM; k++) sm[wid][k] = acc[k];
    __syncthreads();
    if (threadIdx.x < NSUM) {
        float s = 0.f;
#pragma unroll
        for (int ww = 0; ww < 8; ww++) s += sm[ww][threadIdx.x];
        sfin[threadIdx.x] = s;
    }
    __syncthreads();

    // ---- pose (warp 6, lane 0) — overlaps everything below ----
    if (threadIdx.x == 192) {
        solve_pose(sfin, tsv, tout + b * 16);
    }

    // ---- publish norm partial + grid-wide ticket sync (warp 0) ----
    if (wid == 0) {
        unsigned int ticket = 0;
        if (lane == 0) {
            const float* s = sfin;
            float nq = 3.f * (s[0]*s[0] + s[3]*s[3] + s[5]*s[5])
                     + 6.f * (s[1]*s[1] + s[2]*s[2] + s[4]*s[4]);
#pragma unroll
            for (int k = 6; k < 15; k++) nq += 2.f * s[k] * s[k];
#pragma unroll
            for (int k = 15; k < 18; k++) nq += 6.f * s[k] * s[k];
#pragma unroll
            for (int k = 18; k < 21; k++) nq += 2.f * s[k] * s[k];
            nq += 3.f * s[21] * s[21];
            g_sq[b] = nq;
            __threadfence();
            ticket = atomicAdd(&g_ctr, 1u);
        }
        ticket = __shfl_sync(0xFFFFFFFFu, ticket, 0);
        unsigned int target = ((ticket >> 8) + 1u) << 8;   // next multiple of 256
        while (*((volatile unsigned int*)&g_ctr) < target) { }
        __threadfence();
    }

    // ---- warps 0-5 (192 threads): norm + scaled Q fill ----
    if (threadIdx.x < 192) {
        asm volatile("bar.sync 1, 192;" ::: "memory");

        // per-warp deterministic inv_scale (identical in every warp/block)
        float v = 0.f;
#pragma unroll
        for (int i = 0; i < 8; i++)
            v += __ldcg(&g_sq[lane + 32 * i]);
#pragma unroll
        for (int off = 16; off > 0; off >>= 1)
            v += __shfl_xor_sync(0xFFFFFFFFu, v, off);
        float x = rsqrtf(v);
        x = x * (1.5f - 0.5f * v * x * x);  // Newton refine

        if (threadIdx.x < 169)
            qout[b * 169 + threadIdx.x] = q_entry(sfin, threadIdx.x) * x;
    }
}

// ---------------------------------------------------------------------------
extern "C" void kernel_launch(void* const* d_in, const int* in_sizes, int n_in,
                              void* d_out, int out_size)
{
    const float* src = (const float*)d_in[0];
    const float* trg = (const float*)d_in[1];
    const float* w   = (const float*)d_in[2];
    const float* tsv = (const float*)d_in[3];
    float* out  = (float*)d_out;
    float* tout = out;                 // (B,4,4) = 4096 floats
    float* qout = out + BB * 16;       // (B,13,13) = 43264 floats

    fused_all<<<BB, 256>>>(src, trg, w, tsv, tout, qout);
}